// round 4
// baseline (speedup 1.0000x reference)
#include <cuda_runtime.h>
#include <cuda_bf16.h>
#include <stdint.h>

// ---------------------------------------------------------------------------
// HeteroGraphSAGE, 2 layers, 4 node types, 8 relations.
// agg[d] = Wr * (inv[d] * sum_e w_e * x[src])  -> CSR gather (no atomics) of RAW
// features, written directly in split-bf16 (hi+lo) form; then one K-concat
// tensor-core GEMM per dst type with pre-split weights.
// ---------------------------------------------------------------------------

#define NU 200000
#define NP 100000
#define NC 2000
#define NQ 50000
#define NTOT 352000
#define HID 128

#define NROWS 802000        // total (relation, dst-node) rows
#define ETOT  2400000       // total directed edges
#define NWCHUNK 24          // 8 wsum + 8 W1r + 8 W2r

#define LDS 72              // bf16 elems per smem row (64 data + 8 pad -> 144B stride)
#define LDSB 144
#define SMEM_BYTES (4 * 128 * LDS * 2)   // Ah, Al, Wh, Wl

// scratch (device globals; allocation-free)
__device__ __nv_bfloat16 g_ahi[(size_t)NROWS * HID];   // aggr hi
__device__ __nv_bfloat16 g_alo[(size_t)NROWS * HID];   // aggr lo
__device__ float g_h[(size_t)NTOT * HID];              // hidden after layer 1
__device__ int   g_cnt[NROWS];
__device__ int   g_rowptr[NROWS + 1];
__device__ int   g_cursor[NROWS];
__device__ int   g_srcg[ETOT];
__device__ float g_wg[ETOT];
__device__ int   g_bsums[512];
__device__ float g_wsum[2 * 4 * HID * HID];            // combined Wl per (layer,dst)
__device__ float g_bsum[2 * 4 * HID];
__device__ __nv_bfloat16 g_wh[NWCHUNK * HID * HID];    // pre-split weights hi
__device__ __nv_bfloat16 g_wl[NWCHUNK * HID * HID];    // pre-split weights lo

// ---------------------------------------------------------------------------
// PTX helpers
// ---------------------------------------------------------------------------
#define LDSM4(R, addr)                                                          \
    asm volatile("ldmatrix.sync.aligned.m8n8.x4.shared.b16 {%0,%1,%2,%3}, [%4];" \
                 : "=r"((R)[0]), "=r"((R)[1]), "=r"((R)[2]), "=r"((R)[3])        \
                 : "r"(addr))

#define MMA16816(C, A, B0, B1)                                                  \
    asm volatile("mma.sync.aligned.m16n8k16.row.col.f32.bf16.bf16.f32 "         \
                 "{%0,%1,%2,%3},{%4,%5,%6,%7},{%8,%9},{%0,%1,%2,%3};"           \
                 : "+f"((C)[0]), "+f"((C)[1]), "+f"((C)[2]), "+f"((C)[3])        \
                 : "r"((A)[0]), "r"((A)[1]), "r"((A)[2]), "r"((A)[3]),           \
                   "r"(B0), "r"(B1))

__device__ __forceinline__ uint32_t pack_bf16(__nv_bfloat16 a, __nv_bfloat16 b)
{
    __nv_bfloat162 p = __halves2bfloat162(a, b);
    return *reinterpret_cast<uint32_t*>(&p);
}

__device__ __forceinline__ void split_pair(float x, float y, uint32_t& hi, uint32_t& lo)
{
    __nv_bfloat16 hx = __float2bfloat16(x);
    __nv_bfloat16 hy = __float2bfloat16(y);
    __nv_bfloat16 lx = __float2bfloat16(x - __bfloat162float(hx));
    __nv_bfloat16 ly = __float2bfloat16(y - __bfloat162float(hy));
    hi = pack_bf16(hx, hy);
    lo = pack_bf16(lx, ly);
}

// ---------------------------------------------------------------------------
// Multi-chunk tensor-core GEMM (bf16x3 split):
//   C = bias + A0 @ W0^T + sum_q Aq @ Wq^T
// Chunk 0: A0 fp32 (converted in-kernel). Chunks 1..3: pre-split bf16 hi/lo.
// All W chunks pre-split. Block tile 128x128, 8 warps (4m x 2n).
// ---------------------------------------------------------------------------
struct GemmArgs {
    const float* A0;
    const __nv_bfloat16* Ahi[3];
    const __nv_bfloat16* Alo[3];
    const __nv_bfloat16* Wh[4];
    const __nv_bfloat16* Wl[4];
};

__global__ void __launch_bounds__(256, 2)
gemm_mma(GemmArgs p, int nch, const float* __restrict__ bias,
         float* __restrict__ C, int n, int dorelu)
{
    extern __shared__ __nv_bfloat16 smem[];
    uint32_t sAh_u = (uint32_t)__cvta_generic_to_shared(smem);
    const uint32_t LO_OFF = 128 * LDS * 2;       // bytes hi->lo
    uint32_t sWh_u = sAh_u + 2 * LO_OFF;

    const int tid  = threadIdx.x;
    const int lane = tid & 31;
    const int warp = tid >> 5;
    const int wm = warp >> 1;
    const int wn = warp & 1;
    const int bm = blockIdx.x * 128;

    float c[2][8][4];
#pragma unroll
    for (int i = 0; i < 2; i++)
#pragma unroll
        for (int j = 0; j < 8; j++)
#pragma unroll
            for (int q = 0; q < 4; q++) c[i][j][q] = 0.f;

#pragma unroll
    for (int ch = 0; ch < 4; ch++) {
        if (ch >= nch) break;
        const __nv_bfloat16* Wh = p.Wh[ch];
        const __nv_bfloat16* Wl = p.Wl[ch];

        for (int kb = 0; kb < 128; kb += 64) {
            // ---- A fill ----
            if (ch == 0) {
                // fp32 -> split-bf16 conversion path
#pragma unroll
                for (int it = 0; it < 8; it++) {
                    int idx = tid + it * 256;
                    int r   = idx >> 4;
                    int kc  = (idx & 15) << 2;
                    float4 va = make_float4(0.f, 0.f, 0.f, 0.f);
                    int row = bm + r;
                    if (row < n)
                        va = *(const float4*)(p.A0 + (size_t)row * HID + kb + kc);
                    uint32_t h01, l01, h23, l23;
                    split_pair(va.x, va.y, h01, l01);
                    split_pair(va.z, va.w, h23, l23);
                    size_t so = (size_t)r * LDS + kc;
                    *(uint2*)(smem + so)             = make_uint2(h01, h23);
                    *(uint2*)(smem + 128 * LDS + so) = make_uint2(l01, l23);
                }
            } else {
                // direct copy of pre-split bf16 (16B per load)
                const __nv_bfloat16* Ahi = p.Ahi[ch - 1];
                const __nv_bfloat16* Alo = p.Alo[ch - 1];
                const uint4 z = make_uint4(0, 0, 0, 0);
#pragma unroll
                for (int it = 0; it < 4; it++) {
                    int idx = tid + it * 256;          // 0..1023
                    int r   = idx >> 3;
                    int kc  = (idx & 7) << 3;
                    int row = bm + r;
                    size_t go = (size_t)row * HID + kb + kc;
                    size_t so = (size_t)r * LDS + kc;
                    uint4 vh = (row < n) ? *(const uint4*)(Ahi + go) : z;
                    uint4 vl = (row < n) ? *(const uint4*)(Alo + go) : z;
                    *(uint4*)(smem + so)             = vh;
                    *(uint4*)(smem + 128 * LDS + so) = vl;
                }
            }
            // ---- W fill (always pre-split, direct copy) ----
#pragma unroll
            for (int it = 0; it < 4; it++) {
                int idx = tid + it * 256;
                int r   = idx >> 3;
                int kc  = (idx & 7) << 3;
                size_t go = (size_t)r * HID + kb + kc;
                size_t so = (size_t)r * LDS + kc;
                *(uint4*)(smem + 2 * 128 * LDS + so) = *(const uint4*)(Wh + go);
                *(uint4*)(smem + 3 * 128 * LDS + so) = *(const uint4*)(Wl + go);
            }
            __syncthreads();

            // ---- 4 k-steps of 16 ----
#pragma unroll
            for (int ks = 0; ks < 4; ks++) {
                uint32_t ah[2][4], al[2][4], bh[4][4], bl[4][4];
#pragma unroll
                for (int i = 0; i < 2; i++) {
                    int r   = wm * 32 + i * 16 + (lane & 15);
                    int kby = ks * 32 + ((lane >> 4) << 4);
                    uint32_t ad = sAh_u + r * LDSB + kby;
                    LDSM4(ah[i], ad);
                    LDSM4(al[i], ad + LO_OFF);
                }
#pragma unroll
                for (int pq = 0; pq < 4; pq++) {
                    int nr  = wn * 64 + (2 * pq + (lane >> 4)) * 8 + (lane & 7);
                    int kby = ks * 32 + ((lane >> 3) & 1) * 16;
                    uint32_t ad = sWh_u + nr * LDSB + kby;
                    LDSM4(bh[pq], ad);
                    LDSM4(bl[pq], ad + LO_OFF);
                }
#pragma unroll
                for (int i = 0; i < 2; i++)
#pragma unroll
                    for (int j = 0; j < 8; j++) {
                        const uint32_t* b = bh[j >> 1] + (j & 1) * 2;
                        MMA16816(c[i][j], ah[i], b[0], b[1]);
                    }
#pragma unroll
                for (int i = 0; i < 2; i++)
#pragma unroll
                    for (int j = 0; j < 8; j++) {
                        const uint32_t* b = bl[j >> 1] + (j & 1) * 2;
                        MMA16816(c[i][j], ah[i], b[0], b[1]);
                    }
#pragma unroll
                for (int i = 0; i < 2; i++)
#pragma unroll
                    for (int j = 0; j < 8; j++) {
                        const uint32_t* b = bh[j >> 1] + (j & 1) * 2;
                        MMA16816(c[i][j], al[i], b[0], b[1]);
                    }
            }
            __syncthreads();
        }
    }

    // ---- epilogue ----
    const int g  = lane >> 2;
    const int tq = lane & 3;
#pragma unroll
    for (int i = 0; i < 2; i++) {
#pragma unroll
        for (int half = 0; half < 2; half++) {
            int row = bm + wm * 32 + i * 16 + half * 8 + g;
            if (row >= n) continue;
#pragma unroll
            for (int j = 0; j < 8; j++) {
                int col = wn * 64 + j * 8 + tq * 2;
                float2 v;
                v.x = c[i][j][half * 2 + 0] + bias[col];
                v.y = c[i][j][half * 2 + 1] + bias[col + 1];
                if (dorelu) {
                    v.x = fmaxf(v.x, 0.f);
                    v.y = fmaxf(v.y, 0.f);
                }
                *(float2*)(C + (size_t)row * HID + col) = v;
            }
        }
    }
}

// ---------------------------------------------------------------------------
// CSR build: count -> scan -> fill
// ---------------------------------------------------------------------------
__global__ void count_kernel(const int* __restrict__ dst, int E, int* __restrict__ cnt)
{
    int e = blockIdx.x * blockDim.x + threadIdx.x;
    if (e < E) atomicAdd(&cnt[dst[e]], 1);
}

__global__ void scan1_kernel(const int* __restrict__ cnt, int* __restrict__ rowptr,
                             int* __restrict__ bsums, int n)
{
    __shared__ int wsums[8];
    int base = blockIdx.x * 4096 + threadIdx.x * 16;
    int v[16];
    int s = 0;
#pragma unroll
    for (int i = 0; i < 16; i++) {
        v[i] = (base + i < n) ? cnt[base + i] : 0;
        s += v[i];
    }
    int lane = threadIdx.x & 31, w = threadIdx.x >> 5;
    int ps = s;
#pragma unroll
    for (int o = 1; o < 32; o <<= 1) {
        int t = __shfl_up_sync(0xffffffffu, ps, o);
        if (lane >= o) ps += t;
    }
    if (lane == 31) wsums[w] = ps;
    __syncthreads();
    if (w == 0) {
        int t = (lane < 8) ? wsums[lane] : 0;
#pragma unroll
        for (int o = 1; o < 8; o <<= 1) {
            int u = __shfl_up_sync(0xffffffffu, t, o);
            if (lane >= o) t += u;
        }
        if (lane < 8) wsums[lane] = t;
    }
    __syncthreads();
    int excl = ps - s + (w ? wsums[w - 1] : 0);
    int run = excl;
#pragma unroll
    for (int i = 0; i < 16; i++) {
        if (base + i < n) rowptr[base + i] = run;
        run += v[i];
    }
    if (threadIdx.x == 0) bsums[blockIdx.x] = wsums[7];
}

__global__ void scan2_kernel(int* __restrict__ bsums, int nb)
{
    if (threadIdx.x == 0 && blockIdx.x == 0) {
        int run = 0;
        for (int i = 0; i < nb; i++) {
            int t = bsums[i];
            bsums[i] = run;
            run += t;
        }
    }
}

__global__ void scan3_kernel(int* __restrict__ rowptr, const int* __restrict__ bsums, int n)
{
    int base = blockIdx.x * 4096 + threadIdx.x * 16;
    int off = bsums[blockIdx.x];
#pragma unroll
    for (int i = 0; i < 16; i++)
        if (base + i < n) rowptr[base + i] += off;
    if (blockIdx.x == 0 && threadIdx.x == 0) rowptr[n] = ETOT;
}

__global__ void fill_kernel(const int* __restrict__ src, const int* __restrict__ dst,
                            const float* __restrict__ ew, int E, int rowOff,
                            int* __restrict__ cursor,
                            int* __restrict__ srcg, float* __restrict__ wg)
{
    int e = blockIdx.x * blockDim.x + threadIdx.x;
    if (e >= E) return;
    int slot = atomicAdd(&cursor[rowOff + dst[e]], 1);
    srcg[slot] = src[e];
    wg[slot]   = ew[e];
}

// ---------------------------------------------------------------------------
// Combined Wl / bias per (layer, dst type).
// ---------------------------------------------------------------------------
__global__ void wsum_kernel(const float* __restrict__ W1l, const float* __restrict__ b1,
                            const float* __restrict__ W2l, const float* __restrict__ b2,
                            float* __restrict__ wsum, float* __restrict__ bsum)
{
    const int dstT[8] = {1, 0, 3, 0, 1, 3, 2, 1};
    int idx = blockIdx.x * blockDim.x + threadIdx.x;
    if (idx >= 2 * 4 * HID * HID) return;
    int l  = idx / (4 * HID * HID);
    int r  = idx % (4 * HID * HID);
    int d  = r / (HID * HID);
    int ij = r % (HID * HID);
    const float* W = l ? W2l : W1l;
    float s = 0.f;
#pragma unroll
    for (int t = 0; t < 8; t++)
        if (dstT[t] == d) s += W[t * HID * HID + ij];
    wsum[idx] = s;
    if (ij < HID) {
        const float* B = l ? b2 : b1;
        float sb = 0.f;
#pragma unroll
        for (int t = 0; t < 8; t++)
            if (dstT[t] == d) sb += B[t * HID + ij];
        bsum[(l * 4 + d) * HID + ij] = sb;
    }
}

// ---------------------------------------------------------------------------
// Pre-split all 24 weight chunks into bf16 hi/lo.
// chunk 0..7: wsum(layer,dst); 8..15: W1r[t]; 16..23: W2r[t]
// ---------------------------------------------------------------------------
__global__ void wsplit_kernel(const float* __restrict__ wsum,
                              const float* __restrict__ W1r,
                              const float* __restrict__ W2r,
                              __nv_bfloat16* __restrict__ wh,
                              __nv_bfloat16* __restrict__ wl)
{
    int idx = blockIdx.x * blockDim.x + threadIdx.x;
    if (idx >= NWCHUNK * HID * HID) return;
    int c  = idx >> 14;
    int ij = idx & 16383;
    float v = (c < 8) ? wsum[idx]
            : (c < 16) ? W1r[(c - 8) * HID * HID + ij]
                       : W2r[(c - 16) * HID * HID + ij];
    __nv_bfloat16 h = __float2bfloat16(v);
    wh[idx] = h;
    wl[idx] = __float2bfloat16(v - __bfloat162float(h));
}

// ---------------------------------------------------------------------------
// CSR gather over ALL relations: one warp per (relation,dst) row — no atomics.
// Output written directly in split-bf16 form.
// ---------------------------------------------------------------------------
struct GatherArgs { const float* x[8]; int rowEnd[8]; };

__global__ void gather_kernel(GatherArgs ga,
                              const int* __restrict__ rowptr,
                              const int* __restrict__ srcg,
                              const float* __restrict__ wg,
                              __nv_bfloat16* __restrict__ ahi,
                              __nv_bfloat16* __restrict__ alo)
{
    int row = (blockIdx.x * blockDim.x + threadIdx.x) >> 5;
    int lane = threadIdx.x & 31;
    if (row >= NROWS) return;

    int t = 0;
#pragma unroll
    for (int q = 0; q < 7; q++)
        if (row >= ga.rowEnd[q] && t == q) t = q + 1;
    const float* x = ga.x[t];

    int e0 = rowptr[row], e1 = rowptr[row + 1];

    float4 acc = make_float4(0.f, 0.f, 0.f, 0.f);
    int e = e0;
    for (; e + 1 < e1; e += 2) {
        int   s0 = srcg[e],   s1 = srcg[e + 1];
        float w0 = wg[e],     w1 = wg[e + 1];
        float4 v0 = *((const float4*)(x + (size_t)s0 * HID) + lane);
        float4 v1 = *((const float4*)(x + (size_t)s1 * HID) + lane);
        acc.x += w0 * v0.x + w1 * v1.x;
        acc.y += w0 * v0.y + w1 * v1.y;
        acc.z += w0 * v0.z + w1 * v1.z;
        acc.w += w0 * v0.w + w1 * v1.w;
    }
    if (e < e1) {
        int s0 = srcg[e];
        float w0 = wg[e];
        float4 v0 = *((const float4*)(x + (size_t)s0 * HID) + lane);
        acc.x += w0 * v0.x;
        acc.y += w0 * v0.y;
        acc.z += w0 * v0.z;
        acc.w += w0 * v0.w;
    }
    float invd = 1.f / fmaxf((float)(e1 - e0), 1.f);
    acc.x *= invd; acc.y *= invd; acc.z *= invd; acc.w *= invd;

    uint32_t h01, l01, h23, l23;
    split_pair(acc.x, acc.y, h01, l01);
    split_pair(acc.z, acc.w, h23, l23);
    size_t off = (size_t)row * HID + lane * 4;
    *(uint2*)(ahi + off) = make_uint2(h01, h23);
    *(uint2*)(alo + off) = make_uint2(l01, l23);
}

// ---------------------------------------------------------------------------
// Host launch
// ---------------------------------------------------------------------------
struct Rel { int srcT, dstT, E, eiIdx, rev, ewIdx, rowOff; };

extern "C" void kernel_launch(void* const* d_in, const int* in_sizes, int n_in,
                              void* d_out, int out_size)
{
    (void)in_sizes; (void)n_in; (void)out_size;

    static const Rel rels[8] = {
        {0, 1, 500000, 18, 0, 10, 0},       // user -> product  (buys)
        {1, 0, 500000, 18, 1, 11, 100000},  // product -> user  (rev buys)
        {0, 3, 300000, 19, 0, 12, 300000},  // user -> query    (searches)
        {3, 0, 300000, 19, 1, 13, 350000},  // query -> user    (rev searches)
        {3, 1, 300000, 20, 0, 14, 550000},  // query -> product (matches)
        {1, 3, 300000, 20, 1, 15, 650000},  // product -> query (rev matches)
        {1, 2, 100000, 21, 0, 16, 700000},  // product -> category (in)
        {2, 1, 100000, 21, 1, 17, 702000},  // category -> product (rev in)
    };
    static const int relForDst[4][3] = { {1, 3, -1}, {0, 4, 7}, {6, -1, -1}, {2, 5, -1} };
    static const int nRelForDst[4]   = { 2, 3, 1, 2 };
    static const int    nodeN[4]   = {NU, NP, NC, NQ};
    static const size_t nodeOff[4] = {0, NU, NU + NP, NU + NP + NC};

    cudaFuncSetAttribute(gemm_mma, cudaFuncAttributeMaxDynamicSharedMemorySize, SMEM_BYTES);

    float *h, *wsum, *bsum, *wg;
    __nv_bfloat16 *ahi, *alo, *wh, *wl;
    int *cnt, *rowptr, *cursor, *srcg, *bsums;
    cudaGetSymbolAddress((void**)&ahi,    g_ahi);
    cudaGetSymbolAddress((void**)&alo,    g_alo);
    cudaGetSymbolAddress((void**)&h,      g_h);
    cudaGetSymbolAddress((void**)&cnt,    g_cnt);
    cudaGetSymbolAddress((void**)&rowptr, g_rowptr);
    cudaGetSymbolAddress((void**)&cursor, g_cursor);
    cudaGetSymbolAddress((void**)&srcg,   g_srcg);
    cudaGetSymbolAddress((void**)&wg,     g_wg);
    cudaGetSymbolAddress((void**)&bsums,  g_bsums);
    cudaGetSymbolAddress((void**)&wsum,   g_wsum);
    cudaGetSymbolAddress((void**)&bsum,   g_bsum);
    cudaGetSymbolAddress((void**)&wh,     g_wh);
    cudaGetSymbolAddress((void**)&wl,     g_wl);

    const float* x0[4] = { (const float*)d_in[0], (const float*)d_in[1],
                           (const float*)d_in[2], (const float*)d_in[3] };
    const float* W1l = (const float*)d_in[4];
    const float* b1  = (const float*)d_in[5];
    const float* W1r = (const float*)d_in[6];
    const float* W2l = (const float*)d_in[7];
    const float* b2  = (const float*)d_in[8];
    const float* W2r = (const float*)d_in[9];
    float* out = (float*)d_out;

    cudaStream_t st = 0;
    const int NSCAN = (NROWS + 4095) / 4096;

    // ---- CSR build (layer-invariant) ----
    cudaMemsetAsync(cnt, 0, NROWS * sizeof(int), st);
    for (int t = 0; t < 8; t++) {
        const Rel& r = rels[t];
        const int* ei  = (const int*)d_in[r.eiIdx];
        const int* dst = r.rev ? ei : ei + r.E;
        count_kernel<<<(r.E + 255) / 256, 256, 0, st>>>(dst, r.E, cnt + r.rowOff);
    }
    scan1_kernel<<<NSCAN, 256, 0, st>>>(cnt, rowptr, bsums, NROWS);
    scan2_kernel<<<1, 32, 0, st>>>(bsums, NSCAN);
    scan3_kernel<<<NSCAN, 256, 0, st>>>(rowptr, bsums, NROWS);
    cudaMemcpyAsync(cursor, rowptr, NROWS * sizeof(int), cudaMemcpyDeviceToDevice, st);
    for (int t = 0; t < 8; t++) {
        const Rel& r = rels[t];
        const int* ei  = (const int*)d_in[r.eiIdx];
        const int* src = r.rev ? ei + r.E : ei;
        const int* dst = r.rev ? ei       : ei + r.E;
        const float* ew = (const float*)d_in[r.ewIdx];
        fill_kernel<<<(r.E + 255) / 256, 256, 0, st>>>(src, dst, ew, r.E, r.rowOff,
                                                       cursor, srcg, wg);
    }

    // ---- combined Wl / bias, then pre-split all weights ----
    wsum_kernel<<<(2 * 4 * HID * HID + 255) / 256, 256, 0, st>>>(W1l, b1, W2l, b2, wsum, bsum);
    wsplit_kernel<<<(NWCHUNK * HID * HID + 255) / 256, 256, 0, st>>>(wsum, W1r, W2r, wh, wl);

    // ---- two layers ----
    for (int layer = 0; layer < 2; layer++) {
        // gather raw features for all relations in one launch
        GatherArgs ga;
        for (int t = 0; t < 8; t++) {
            const Rel& r = rels[t];
            ga.x[t] = layer ? (h + nodeOff[r.srcT] * HID) : x0[r.srcT];
            ga.rowEnd[t] = r.rowOff + nodeN[r.dstT];
        }
        gather_kernel<<<(NROWS * 32 + 255) / 256, 256, 0, st>>>(ga, rowptr, srcg, wg, ahi, alo);

        // one K-concat GEMM per dst type
        for (int d = 0; d < 4; d++) {
            GemmArgs p;
            p.A0 = layer ? (h + nodeOff[d] * HID) : x0[d];
            p.Wh[0] = wh + (size_t)(layer * 4 + d) * HID * HID;
            p.Wl[0] = wl + (size_t)(layer * 4 + d) * HID * HID;
            for (int q = 0; q < 3; q++) { p.Ahi[q] = nullptr; p.Alo[q] = nullptr;
                                          p.Wh[q+1] = nullptr; p.Wl[q+1] = nullptr; }
            for (int q = 0; q < nRelForDst[d]; q++) {
                int t = relForDst[d][q];
                p.Ahi[q] = ahi + (size_t)rels[t].rowOff * HID;
                p.Alo[q] = alo + (size_t)rels[t].rowOff * HID;
                p.Wh[q + 1] = wh + (size_t)(8 + layer * 8 + t) * HID * HID;
                p.Wl[q + 1] = wl + (size_t)(8 + layer * 8 + t) * HID * HID;
            }
            int nch = 1 + nRelForDst[d];
            float* C = layer ? (out + nodeOff[d] * HID) : (h + nodeOff[d] * HID);
            gemm_mma<<<(nodeN[d] + 127) / 128, 256, SMEM_BYTES, st>>>(
                p, nch, bsum + (layer * 4 + d) * HID, C, nodeN[d], layer == 0 ? 1 : 0);
        }
    }
}

// round 5
// speedup vs baseline: 1.2296x; 1.2296x over previous
#include <cuda_runtime.h>
#include <cuda_bf16.h>
#include <stdint.h>

// ---------------------------------------------------------------------------
// HeteroGraphSAGE, 2 layers, 4 node types, 8 relations.
// agg[d] = Wr * (inv[d] * sum_e w_e * x[src])  -> CSR gather (no atomics) of RAW
// features, written directly in split-bf16 (hi+lo) form; then one K-concat
// tensor-core GEMM per dst type with pre-split weights.
// All kernel-parameter pointers are selected via compile-time-resolvable
// ternaries (NO dynamic indexing of param arrays -> no local-memory spill).
// ---------------------------------------------------------------------------

#define NU 200000
#define NP 100000
#define NC 2000
#define NQ 50000
#define NTOT 352000
#define HID 128

#define NROWS 802000        // total (relation, dst-node) rows
#define ETOT  2400000       // total directed edges
#define NWCHUNK 24          // 8 wsum + 8 W1r + 8 W2r

#define LDS 72              // bf16 elems per smem row (64 data + 8 pad -> 144B stride)
#define LDSB 144
#define SMEM_BYTES (4 * 128 * LDS * 2)   // Ah, Al, Wh, Wl

// scratch (device globals; allocation-free)
__device__ __nv_bfloat16 g_ahi[(size_t)NROWS * HID];   // aggr hi
__device__ __nv_bfloat16 g_alo[(size_t)NROWS * HID];   // aggr lo
__device__ float g_h[(size_t)NTOT * HID];              // hidden after layer 1
__device__ int   g_cnt[NROWS];
__device__ int   g_rowptr[NROWS + 1];
__device__ int   g_cursor[NROWS];
__device__ int   g_srcg[ETOT];
__device__ float g_wg[ETOT];
__device__ int   g_bsums[512];
__device__ float g_wsum[2 * 4 * HID * HID];            // combined Wl per (layer,dst)
__device__ float g_bsum[2 * 4 * HID];
__device__ __nv_bfloat16 g_wh[NWCHUNK * HID * HID];    // pre-split weights hi
__device__ __nv_bfloat16 g_wl[NWCHUNK * HID * HID];    // pre-split weights lo

// ---------------------------------------------------------------------------
// PTX helpers
// ---------------------------------------------------------------------------
#define LDSM4(R, addr)                                                          \
    asm volatile("ldmatrix.sync.aligned.m8n8.x4.shared.b16 {%0,%1,%2,%3}, [%4];" \
                 : "=r"((R)[0]), "=r"((R)[1]), "=r"((R)[2]), "=r"((R)[3])        \
                 : "r"(addr))

#define MMA16816(C, A, B0, B1)                                                  \
    asm volatile("mma.sync.aligned.m16n8k16.row.col.f32.bf16.bf16.f32 "         \
                 "{%0,%1,%2,%3},{%4,%5,%6,%7},{%8,%9},{%0,%1,%2,%3};"           \
                 : "+f"((C)[0]), "+f"((C)[1]), "+f"((C)[2]), "+f"((C)[3])        \
                 : "r"((A)[0]), "r"((A)[1]), "r"((A)[2]), "r"((A)[3]),           \
                   "r"(B0), "r"(B1))

__device__ __forceinline__ uint32_t pack_bf16(__nv_bfloat16 a, __nv_bfloat16 b)
{
    __nv_bfloat162 p = __halves2bfloat162(a, b);
    return *reinterpret_cast<uint32_t*>(&p);
}

__device__ __forceinline__ void split_pair(float x, float y, uint32_t& hi, uint32_t& lo)
{
    __nv_bfloat16 hx = __float2bfloat16(x);
    __nv_bfloat16 hy = __float2bfloat16(y);
    __nv_bfloat16 lx = __float2bfloat16(x - __bfloat162float(hx));
    __nv_bfloat16 ly = __float2bfloat16(y - __bfloat162float(hy));
    hi = pack_bf16(hx, hy);
    lo = pack_bf16(lx, ly);
}

// ---------------------------------------------------------------------------
// Multi-chunk tensor-core GEMM (bf16x3 split):
//   C = bias + A0 @ W0^T + sum_q Aq @ Wq^T
// Chunk 0: A0 fp32 (converted in-kernel). Chunks 1..3: pre-split bf16 hi/lo.
// All W chunks pre-split. Block tile 128x128, 8 warps (4m x 2n).
// ---------------------------------------------------------------------------
struct GemmArgs {
    const float* A0;
    const __nv_bfloat16 *A1h, *A1l, *A2h, *A2l, *A3h, *A3l;
    const __nv_bfloat16 *W0h, *W0l, *W1h, *W1l, *W2h, *W2l, *W3h, *W3l;
};

__global__ void __launch_bounds__(256, 2)
gemm_mma(GemmArgs p, int nch, const float* __restrict__ bias,
         float* __restrict__ C, int n, int dorelu)
{
    extern __shared__ __nv_bfloat16 smem[];
    uint32_t sAh_u = (uint32_t)__cvta_generic_to_shared(smem);
    const uint32_t LO_OFF = 128 * LDS * 2;       // bytes hi->lo
    uint32_t sWh_u = sAh_u + 2 * LO_OFF;

    const int tid  = threadIdx.x;
    const int lane = tid & 31;
    const int warp = tid >> 5;
    const int wm = warp >> 1;
    const int wn = warp & 1;
    const int bm = blockIdx.x * 128;

    float c[2][8][4];
#pragma unroll
    for (int i = 0; i < 2; i++)
#pragma unroll
        for (int j = 0; j < 8; j++)
#pragma unroll
            for (int q = 0; q < 4; q++) c[i][j][q] = 0.f;

#pragma unroll
    for (int ch = 0; ch < 4; ch++) {
        if (ch < nch) {
            // compile-time pointer selection per unrolled iteration
            const __nv_bfloat16* Wh = (ch == 0) ? p.W0h : (ch == 1) ? p.W1h
                                    : (ch == 2) ? p.W2h : p.W3h;
            const __nv_bfloat16* Wl = (ch == 0) ? p.W0l : (ch == 1) ? p.W1l
                                    : (ch == 2) ? p.W2l : p.W3l;
            const __nv_bfloat16* Ahi = (ch == 1) ? p.A1h : (ch == 2) ? p.A2h : p.A3h;
            const __nv_bfloat16* Alo = (ch == 1) ? p.A1l : (ch == 2) ? p.A2l : p.A3l;

            for (int kb = 0; kb < 128; kb += 64) {
                // ---- A fill ----
                if (ch == 0) {
                    // fp32 -> split-bf16 conversion path
#pragma unroll
                    for (int it = 0; it < 8; it++) {
                        int idx = tid + it * 256;
                        int r   = idx >> 4;
                        int kc  = (idx & 15) << 2;
                        float4 va = make_float4(0.f, 0.f, 0.f, 0.f);
                        int row = bm + r;
                        if (row < n)
                            va = *(const float4*)(p.A0 + (size_t)row * HID + kb + kc);
                        uint32_t h01, l01, h23, l23;
                        split_pair(va.x, va.y, h01, l01);
                        split_pair(va.z, va.w, h23, l23);
                        size_t so = (size_t)r * LDS + kc;
                        *(uint2*)(smem + so)             = make_uint2(h01, h23);
                        *(uint2*)(smem + 128 * LDS + so) = make_uint2(l01, l23);
                    }
                } else {
                    // direct copy of pre-split bf16 (16B per load)
                    const uint4 z = make_uint4(0, 0, 0, 0);
#pragma unroll
                    for (int it = 0; it < 4; it++) {
                        int idx = tid + it * 256;          // 0..1023
                        int r   = idx >> 3;
                        int kc  = (idx & 7) << 3;
                        int row = bm + r;
                        size_t go = (size_t)row * HID + kb + kc;
                        size_t so = (size_t)r * LDS + kc;
                        uint4 vh = (row < n) ? *(const uint4*)(Ahi + go) : z;
                        uint4 vl = (row < n) ? *(const uint4*)(Alo + go) : z;
                        *(uint4*)(smem + so)             = vh;
                        *(uint4*)(smem + 128 * LDS + so) = vl;
                    }
                }
                // ---- W fill (pre-split, direct copy) ----
#pragma unroll
                for (int it = 0; it < 4; it++) {
                    int idx = tid + it * 256;
                    int r   = idx >> 3;
                    int kc  = (idx & 7) << 3;
                    size_t go = (size_t)r * HID + kb + kc;
                    size_t so = (size_t)r * LDS + kc;
                    *(uint4*)(smem + 2 * 128 * LDS + so) = *(const uint4*)(Wh + go);
                    *(uint4*)(smem + 3 * 128 * LDS + so) = *(const uint4*)(Wl + go);
                }
                __syncthreads();

                // ---- 4 k-steps of 16 ----
#pragma unroll
                for (int ks = 0; ks < 4; ks++) {
                    uint32_t ah[2][4], al[2][4], bh[4][4], bl[4][4];
#pragma unroll
                    for (int i = 0; i < 2; i++) {
                        int r   = wm * 32 + i * 16 + (lane & 15);
                        int kby = ks * 32 + ((lane >> 4) << 4);
                        uint32_t ad = sAh_u + r * LDSB + kby;
                        LDSM4(ah[i], ad);
                        LDSM4(al[i], ad + LO_OFF);
                    }
#pragma unroll
                    for (int pq = 0; pq < 4; pq++) {
                        int nr  = wn * 64 + (2 * pq + (lane >> 4)) * 8 + (lane & 7);
                        int kby = ks * 32 + ((lane >> 3) & 1) * 16;
                        uint32_t ad = sWh_u + nr * LDSB + kby;
                        LDSM4(bh[pq], ad);
                        LDSM4(bl[pq], ad + LO_OFF);
                    }
#pragma unroll
                    for (int i = 0; i < 2; i++)
#pragma unroll
                        for (int j = 0; j < 8; j++) {
                            const uint32_t* b = bh[j >> 1] + (j & 1) * 2;
                            MMA16816(c[i][j], ah[i], b[0], b[1]);
                        }
#pragma unroll
                    for (int i = 0; i < 2; i++)
#pragma unroll
                        for (int j = 0; j < 8; j++) {
                            const uint32_t* b = bl[j >> 1] + (j & 1) * 2;
                            MMA16816(c[i][j], ah[i], b[0], b[1]);
                        }
#pragma unroll
                    for (int i = 0; i < 2; i++)
#pragma unroll
                        for (int j = 0; j < 8; j++) {
                            const uint32_t* b = bh[j >> 1] + (j & 1) * 2;
                            MMA16816(c[i][j], al[i], b[0], b[1]);
                        }
                }
                __syncthreads();
            }
        }
    }

    // ---- epilogue ----
    const int g  = lane >> 2;
    const int tq = lane & 3;
#pragma unroll
    for (int i = 0; i < 2; i++) {
#pragma unroll
        for (int half = 0; half < 2; half++) {
            int row = bm + wm * 32 + i * 16 + half * 8 + g;
            if (row >= n) continue;
#pragma unroll
            for (int j = 0; j < 8; j++) {
                int col = wn * 64 + j * 8 + tq * 2;
                float2 v;
                v.x = c[i][j][half * 2 + 0] + bias[col];
                v.y = c[i][j][half * 2 + 1] + bias[col + 1];
                if (dorelu) {
                    v.x = fmaxf(v.x, 0.f);
                    v.y = fmaxf(v.y, 0.f);
                }
                *(float2*)(C + (size_t)row * HID + col) = v;
            }
        }
    }
}

// ---------------------------------------------------------------------------
// CSR build: count -> scan -> fill
// ---------------------------------------------------------------------------
__global__ void count_kernel(const int* __restrict__ dst, int E, int* __restrict__ cnt)
{
    int e = blockIdx.x * blockDim.x + threadIdx.x;
    if (e < E) atomicAdd(&cnt[dst[e]], 1);
}

__global__ void scan1_kernel(const int* __restrict__ cnt, int* __restrict__ rowptr,
                             int* __restrict__ bsums, int n)
{
    __shared__ int wsums[8];
    int base = blockIdx.x * 4096 + threadIdx.x * 16;
    int v[16];
    int s = 0;
#pragma unroll
    for (int i = 0; i < 16; i++) {
        v[i] = (base + i < n) ? cnt[base + i] : 0;
        s += v[i];
    }
    int lane = threadIdx.x & 31, w = threadIdx.x >> 5;
    int ps = s;
#pragma unroll
    for (int o = 1; o < 32; o <<= 1) {
        int t = __shfl_up_sync(0xffffffffu, ps, o);
        if (lane >= o) ps += t;
    }
    if (lane == 31) wsums[w] = ps;
    __syncthreads();
    if (w == 0) {
        int t = (lane < 8) ? wsums[lane] : 0;
#pragma unroll
        for (int o = 1; o < 8; o <<= 1) {
            int u = __shfl_up_sync(0xffffffffu, t, o);
            if (lane >= o) t += u;
        }
        if (lane < 8) wsums[lane] = t;
    }
    __syncthreads();
    int excl = ps - s + (w ? wsums[w - 1] : 0);
    int run = excl;
#pragma unroll
    for (int i = 0; i < 16; i++) {
        if (base + i < n) rowptr[base + i] = run;
        run += v[i];
    }
    if (threadIdx.x == 0) bsums[blockIdx.x] = wsums[7];
}

__global__ void scan2_kernel(int* __restrict__ bsums, int nb)
{
    if (threadIdx.x == 0 && blockIdx.x == 0) {
        int run = 0;
        for (int i = 0; i < nb; i++) {
            int t = bsums[i];
            bsums[i] = run;
            run += t;
        }
    }
}

__global__ void scan3_kernel(int* __restrict__ rowptr, const int* __restrict__ bsums, int n)
{
    int base = blockIdx.x * 4096 + threadIdx.x * 16;
    int off = bsums[blockIdx.x];
#pragma unroll
    for (int i = 0; i < 16; i++)
        if (base + i < n) rowptr[base + i] += off;
    if (blockIdx.x == 0 && threadIdx.x == 0) rowptr[n] = ETOT;
}

__global__ void fill_kernel(const int* __restrict__ src, const int* __restrict__ dst,
                            const float* __restrict__ ew, int E, int rowOff,
                            int* __restrict__ cursor,
                            int* __restrict__ srcg, float* __restrict__ wg)
{
    int e = blockIdx.x * blockDim.x + threadIdx.x;
    if (e >= E) return;
    int slot = atomicAdd(&cursor[rowOff + dst[e]], 1);
    srcg[slot] = src[e];
    wg[slot]   = ew[e];
}

// ---------------------------------------------------------------------------
// Combined Wl / bias per (layer, dst type).
// ---------------------------------------------------------------------------
__global__ void wsum_kernel(const float* __restrict__ W1l, const float* __restrict__ b1,
                            const float* __restrict__ W2l, const float* __restrict__ b2,
                            float* __restrict__ wsum, float* __restrict__ bsum)
{
    const int dstT[8] = {1, 0, 3, 0, 1, 3, 2, 1};
    int idx = blockIdx.x * blockDim.x + threadIdx.x;
    if (idx >= 2 * 4 * HID * HID) return;
    int l  = idx / (4 * HID * HID);
    int r  = idx % (4 * HID * HID);
    int d  = r / (HID * HID);
    int ij = r % (HID * HID);
    const float* W = l ? W2l : W1l;
    float s = 0.f;
#pragma unroll
    for (int t = 0; t < 8; t++)
        if (dstT[t] == d) s += W[t * HID * HID + ij];
    wsum[idx] = s;
    if (ij < HID) {
        const float* B = l ? b2 : b1;
        float sb = 0.f;
#pragma unroll
        for (int t = 0; t < 8; t++)
            if (dstT[t] == d) sb += B[t * HID + ij];
        bsum[(l * 4 + d) * HID + ij] = sb;
    }
}

// ---------------------------------------------------------------------------
// Pre-split all 24 weight chunks into bf16 hi/lo.
// chunk 0..7: wsum(layer,dst); 8..15: W1r[t]; 16..23: W2r[t]
// ---------------------------------------------------------------------------
__global__ void wsplit_kernel(const float* __restrict__ wsum,
                              const float* __restrict__ W1r,
                              const float* __restrict__ W2r,
                              __nv_bfloat16* __restrict__ wh,
                              __nv_bfloat16* __restrict__ wl)
{
    int idx = blockIdx.x * blockDim.x + threadIdx.x;
    if (idx >= NWCHUNK * HID * HID) return;
    int c  = idx >> 14;
    int ij = idx & 16383;
    float v = (c < 8) ? wsum[idx]
            : (c < 16) ? W1r[(c - 8) * HID * HID + ij]
                       : W2r[(c - 16) * HID * HID + ij];
    __nv_bfloat16 h = __float2bfloat16(v);
    wh[idx] = h;
    wl[idx] = __float2bfloat16(v - __bfloat162float(h));
}

// ---------------------------------------------------------------------------
// CSR gather (per relation): one warp per dst row — no atomics.
// Output written directly in split-bf16 form.
// ---------------------------------------------------------------------------
__global__ void gather_kernel(const float* __restrict__ x,
                              const int* __restrict__ rowptr,
                              const int* __restrict__ srcg,
                              const float* __restrict__ wg,
                              __nv_bfloat16* __restrict__ ahi,
                              __nv_bfloat16* __restrict__ alo,
                              int nrows, int rowOff)
{
    int row = (blockIdx.x * blockDim.x + threadIdx.x) >> 5;
    int lane = threadIdx.x & 31;
    if (row >= nrows) return;
    int g = rowOff + row;
    int e0 = rowptr[g], e1 = rowptr[g + 1];

    float4 acc = make_float4(0.f, 0.f, 0.f, 0.f);
    int e = e0;
    for (; e + 1 < e1; e += 2) {
        int   s0 = srcg[e],   s1 = srcg[e + 1];
        float w0 = wg[e],     w1 = wg[e + 1];
        float4 v0 = *((const float4*)(x + (size_t)s0 * HID) + lane);
        float4 v1 = *((const float4*)(x + (size_t)s1 * HID) + lane);
        acc.x += w0 * v0.x + w1 * v1.x;
        acc.y += w0 * v0.y + w1 * v1.y;
        acc.z += w0 * v0.z + w1 * v1.z;
        acc.w += w0 * v0.w + w1 * v1.w;
    }
    if (e < e1) {
        int s0 = srcg[e];
        float w0 = wg[e];
        float4 v0 = *((const float4*)(x + (size_t)s0 * HID) + lane);
        acc.x += w0 * v0.x;
        acc.y += w0 * v0.y;
        acc.z += w0 * v0.z;
        acc.w += w0 * v0.w;
    }
    float invd = 1.f / fmaxf((float)(e1 - e0), 1.f);
    acc.x *= invd; acc.y *= invd; acc.z *= invd; acc.w *= invd;

    uint32_t h01, l01, h23, l23;
    split_pair(acc.x, acc.y, h01, l01);
    split_pair(acc.z, acc.w, h23, l23);
    size_t off = (size_t)g * HID + lane * 4;
    *(uint2*)(ahi + off) = make_uint2(h01, h23);
    *(uint2*)(alo + off) = make_uint2(l01, l23);
}

// ---------------------------------------------------------------------------
// Host launch
// ---------------------------------------------------------------------------
struct Rel { int srcT, dstT, E, eiIdx, rev, ewIdx, rowOff; };

extern "C" void kernel_launch(void* const* d_in, const int* in_sizes, int n_in,
                              void* d_out, int out_size)
{
    (void)in_sizes; (void)n_in; (void)out_size;

    static const Rel rels[8] = {
        {0, 1, 500000, 18, 0, 10, 0},       // user -> product  (buys)
        {1, 0, 500000, 18, 1, 11, 100000},  // product -> user  (rev buys)
        {0, 3, 300000, 19, 0, 12, 300000},  // user -> query    (searches)
        {3, 0, 300000, 19, 1, 13, 350000},  // query -> user    (rev searches)
        {3, 1, 300000, 20, 0, 14, 550000},  // query -> product (matches)
        {1, 3, 300000, 20, 1, 15, 650000},  // product -> query (rev matches)
        {1, 2, 100000, 21, 0, 16, 700000},  // product -> category (in)
        {2, 1, 100000, 21, 1, 17, 702000},  // category -> product (rev in)
    };
    static const int relForDst[4][3] = { {1, 3, -1}, {0, 4, 7}, {6, -1, -1}, {2, 5, -1} };
    static const int nRelForDst[4]   = { 2, 3, 1, 2 };
    static const int    nodeN[4]   = {NU, NP, NC, NQ};
    static const size_t nodeOff[4] = {0, NU, NU + NP, NU + NP + NC};

    cudaFuncSetAttribute(gemm_mma, cudaFuncAttributeMaxDynamicSharedMemorySize, SMEM_BYTES);

    float *h, *wsum, *bsum, *wg;
    __nv_bfloat16 *ahi, *alo, *wh, *wl;
    int *cnt, *rowptr, *cursor, *srcg, *bsums;
    cudaGetSymbolAddress((void**)&ahi,    g_ahi);
    cudaGetSymbolAddress((void**)&alo,    g_alo);
    cudaGetSymbolAddress((void**)&h,      g_h);
    cudaGetSymbolAddress((void**)&cnt,    g_cnt);
    cudaGetSymbolAddress((void**)&rowptr, g_rowptr);
    cudaGetSymbolAddress((void**)&cursor, g_cursor);
    cudaGetSymbolAddress((void**)&srcg,   g_srcg);
    cudaGetSymbolAddress((void**)&wg,     g_wg);
    cudaGetSymbolAddress((void**)&bsums,  g_bsums);
    cudaGetSymbolAddress((void**)&wsum,   g_wsum);
    cudaGetSymbolAddress((void**)&bsum,   g_bsum);
    cudaGetSymbolAddress((void**)&wh,     g_wh);
    cudaGetSymbolAddress((void**)&wl,     g_wl);

    const float* x0[4] = { (const float*)d_in[0], (const float*)d_in[1],
                           (const float*)d_in[2], (const float*)d_in[3] };
    const float* W1l = (const float*)d_in[4];
    const float* b1  = (const float*)d_in[5];
    const float* W1r = (const float*)d_in[6];
    const float* W2l = (const float*)d_in[7];
    const float* b2  = (const float*)d_in[8];
    const float* W2r = (const float*)d_in[9];
    float* out = (float*)d_out;

    cudaStream_t st = 0;
    const int NSCAN = (NROWS + 4095) / 4096;

    // ---- CSR build (layer-invariant) ----
    cudaMemsetAsync(cnt, 0, NROWS * sizeof(int), st);
    for (int t = 0; t < 8; t++) {
        const Rel& r = rels[t];
        const int* ei  = (const int*)d_in[r.eiIdx];
        const int* dst = r.rev ? ei : ei + r.E;
        count_kernel<<<(r.E + 255) / 256, 256, 0, st>>>(dst, r.E, cnt + r.rowOff);
    }
    scan1_kernel<<<NSCAN, 256, 0, st>>>(cnt, rowptr, bsums, NROWS);
    scan2_kernel<<<1, 32, 0, st>>>(bsums, NSCAN);
    scan3_kernel<<<NSCAN, 256, 0, st>>>(rowptr, bsums, NROWS);
    cudaMemcpyAsync(cursor, rowptr, NROWS * sizeof(int), cudaMemcpyDeviceToDevice, st);
    for (int t = 0; t < 8; t++) {
        const Rel& r = rels[t];
        const int* ei  = (const int*)d_in[r.eiIdx];
        const int* src = r.rev ? ei + r.E : ei;
        const int* dst = r.rev ? ei       : ei + r.E;
        const float* ew = (const float*)d_in[r.ewIdx];
        fill_kernel<<<(r.E + 255) / 256, 256, 0, st>>>(src, dst, ew, r.E, r.rowOff,
                                                       cursor, srcg, wg);
    }

    // ---- combined Wl / bias, then pre-split all weights ----
    wsum_kernel<<<(2 * 4 * HID * HID + 255) / 256, 256, 0, st>>>(W1l, b1, W2l, b2, wsum, bsum);
    wsplit_kernel<<<(NWCHUNK * HID * HID + 255) / 256, 256, 0, st>>>(wsum, W1r, W2r, wh, wl);

    // ---- two layers ----
    for (int layer = 0; layer < 2; layer++) {
        // gather raw features per relation (no atomics)
        for (int t = 0; t < 8; t++) {
            const Rel& r = rels[t];
            const float* x = layer ? (h + nodeOff[r.srcT] * HID) : x0[r.srcT];
            int nrows = nodeN[r.dstT];
            gather_kernel<<<(nrows * 32 + 255) / 256, 256, 0, st>>>(
                x, rowptr, srcg, wg, ahi, alo, nrows, r.rowOff);
        }

        // one K-concat GEMM per dst type
        for (int d = 0; d < 4; d++) {
            const __nv_bfloat16 *Ah[3] = {nullptr, nullptr, nullptr};
            const __nv_bfloat16 *Al[3] = {nullptr, nullptr, nullptr};
            const __nv_bfloat16 *Whp[4] = {nullptr, nullptr, nullptr, nullptr};
            const __nv_bfloat16 *Wlp[4] = {nullptr, nullptr, nullptr, nullptr};
            Whp[0] = wh + (size_t)(layer * 4 + d) * HID * HID;
            Wlp[0] = wl + (size_t)(layer * 4 + d) * HID * HID;
            for (int q = 0; q < nRelForDst[d]; q++) {
                int t = relForDst[d][q];
                Ah[q] = ahi + (size_t)rels[t].rowOff * HID;
                Al[q] = alo + (size_t)rels[t].rowOff * HID;
                Whp[q + 1] = wh + (size_t)(8 + layer * 8 + t) * HID * HID;
                Wlp[q + 1] = wl + (size_t)(8 + layer * 8 + t) * HID * HID;
            }
            GemmArgs p;
            p.A0  = layer ? (h + nodeOff[d] * HID) : x0[d];
            p.A1h = Ah[0]; p.A1l = Al[0];
            p.A2h = Ah[1]; p.A2l = Al[1];
            p.A3h = Ah[2]; p.A3l = Al[2];
            p.W0h = Whp[0]; p.W0l = Wlp[0];
            p.W1h = Whp[1]; p.W1l = Wlp[1];
            p.W2h = Whp[2]; p.W2l = Wlp[2];
            p.W3h = Whp[3]; p.W3l = Wlp[3];
            int nch = 1 + nRelForDst[d];
            float* C = layer ? (out + nodeOff[d] * HID) : (h + nodeOff[d] * HID);
            gemm_mma<<<(nodeN[d] + 127) / 128, 256, SMEM_BYTES, st>>>(
                p, nch, bsum + (layer * 4 + d) * HID, C, nodeN[d], layer == 0 ? 1 : 0);
        }
    }
}